// round 12
// baseline (speedup 1.0000x reference)
#include <cuda_runtime.h>
#include <math.h>
#include <stdint.h>

#define NB   4
#define SEQ  2048
#define HID  1024
#define FAC  256
#define NHD  16
#define DK   64
#define ROWS (NB*SEQ)   /* 8192 */
#define BH   (NB*NHD)   /* 64   */

/* linear tiling: 128x64 block, 8 warps of 32x32 (R7 geometry), smem 2-stage */
#define BM 128
#define BN 64
#define BK 32
#define LDA  36
#define LDBN 36
#define LIN_AS (BM*LDA)                    /* 4608 floats per stage */
#define LIN_BS (BN*LDBN)                   /* 2304 floats per stage */
#define LIN_SMEM ((2*LIN_AS + 2*LIN_BS)*4) /* 55296 B */

/* flash geometry (R7, unchanged) */
#define KT   32
#define NCH  (SEQ/KT)    /* 64 */
#define LDQ  68
#define LDK  68
#define LDV  36
#define LDP  36
#define OFF_Q   0
#define OFF_K   (128*LDQ)                 /* 8704  */
#define OFF_V   (OFF_K + 2*KT*LDK)        /* 13056 */
#define OFF_P   (OFF_V + 2*DK*LDV)        /* 17664 */
#define OFF_MB  (OFF_P + 128*LDP)         /* 22272 */
#define FLASH_FLOATS (OFF_MB + 2*KT)      /* 22336 */
#define FLASH_SMEM   (FLASH_FLOATS*4)     /* 89344 B */

/* ---------------- scratch ------------------------------------------------ */
__device__ float g_q  [ROWS*HID];
__device__ float g_k  [ROWS*HID];
__device__ float g_vt [BH*DK*SEQ];   /* V transposed: [bh][d][token] */
__device__ float g_h  [ROWS*FAC];
__device__ float g_cv [ROWS*HID];

/* ---------------- helpers ------------------------------------------------ */
__device__ __forceinline__ float tf32r(float x) {
    uint32_t u;
    asm("cvt.rna.tf32.f32 %0, %1;" : "=r"(u) : "f"(x));
    return __uint_as_float(u);
}
__device__ __forceinline__ float4 cvt4(float4 v) {
    v.x = tf32r(v.x); v.y = tf32r(v.y); v.z = tf32r(v.z); v.w = tf32r(v.w);
    return v;
}
__device__ __forceinline__ void mma_tf32(float c[4], const uint32_t a[4], const uint32_t b[2]) {
    asm volatile(
        "mma.sync.aligned.m16n8k8.row.col.f32.tf32.tf32.f32 "
        "{%0,%1,%2,%3}, {%4,%5,%6,%7}, {%8,%9}, {%0,%1,%2,%3};"
        : "+f"(c[0]), "+f"(c[1]), "+f"(c[2]), "+f"(c[3])
        : "r"(a[0]), "r"(a[1]), "r"(a[2]), "r"(a[3]), "r"(b[0]), "r"(b[1]));
}
__device__ __forceinline__ void ldsm4(uint32_t f[4], uint32_t addr) {
    asm volatile("ldmatrix.sync.aligned.m8n8.x4.shared.b16 {%0,%1,%2,%3}, [%4];"
        : "=r"(f[0]), "=r"(f[1]), "=r"(f[2]), "=r"(f[3]) : "r"(addr));
}
__device__ __forceinline__ uint32_t smem_u32(const void* p) {
    return (uint32_t)__cvta_generic_to_shared(p);
}
__device__ __forceinline__ void cpa16(uint32_t dst, const void* src) {
    asm volatile("cp.async.cg.shared.global [%0], [%1], 16;" :: "r"(dst), "l"(src));
}
#define CPA_COMMIT() asm volatile("cp.async.commit_group;" ::: "memory")
#define CPA_WAIT0()  asm volatile("cp.async.wait_group 0;" ::: "memory")

__device__ __forceinline__ uint32_t frag_base_m(uint32_t base, int row0, int lane, int ld) {
    int lr = lane & 7, sel = lane >> 3;
    int row = row0 + lr + ((sel & 1) << 3);
    int col = (sel & 2) << 1;
    return base + (uint32_t)(row*ld + col)*4u;
}
__device__ __forceinline__ uint32_t frag_base_n(uint32_t base, int n0, int lane, int ld) {
    int lr = lane & 7, sel = lane >> 3;
    int row = n0 + lr + ((sel & 2) << 2);
    int col = (sel & 1) << 2;
    return base + (uint32_t)(row*ld + col)*4u;
}

#define MMA_CHUNK(aB0, aB1, bB0, bB1, acc)                                    \
    _Pragma("unroll")                                                         \
    for (int kk = 0; kk < BK; kk += 8) {                                      \
        uint32_t af0[4], af1[4], bq0[4], bq1[4];                              \
        ldsm4(af0, (aB0) + kk*4);                                             \
        ldsm4(af1, (aB1) + kk*4);                                             \
        ldsm4(bq0, (bB0) + kk*4);                                             \
        ldsm4(bq1, (bB1) + kk*4);                                             \
        mma_tf32(acc[0][0], af0, &bq0[0]);                                    \
        mma_tf32(acc[0][1], af0, &bq0[2]);                                    \
        mma_tf32(acc[0][2], af0, &bq1[0]);                                    \
        mma_tf32(acc[0][3], af0, &bq1[2]);                                    \
        mma_tf32(acc[1][0], af1, &bq0[0]);                                    \
        mma_tf32(acc[1][1], af1, &bq0[2]);                                    \
        mma_tf32(acc[1][2], af1, &bq1[0]);                                    \
        mma_tf32(acc[1][3], af1, &bq1[2]);                                    \
    }

/* =================== TF32 linear, smem double-buffer, 1 barrier/chunk ====
   act: 0 = bias; 1 = bias+leaky(0.2); 2 = bias+tf32 round;
        3 = bias+tf32 round + TRANSPOSED store into Vt[bh][d][token];
        4 = bias, *0.125, tf32 round (Q prescale — exact power of 2)       */
__global__ void __launch_bounds__(256, 3) linear_tc(
    const float* __restrict__ A, const float* __restrict__ W,
    const float* __restrict__ bias, float* __restrict__ C,
    int M, int N, int K, int act)
{
    extern __shared__ __align__(16) float lsm[];
    const uint32_t smBase = smem_u32(lsm);
    const uint32_t smA[2] = { smBase, smBase + LIN_AS*4u };
    const uint32_t smB[2] = { smBase + 2u*LIN_AS*4u, smBase + (2u*LIN_AS + LIN_BS)*4u };

    const int tid = threadIdx.x;
    const int row0 = blockIdx.x * BM;
    const int col0 = blockIdx.y * BN;

    const int arow = tid >> 3, acol = (tid & 7) << 2;
    const int bn = tid & 63, bk4 = (tid >> 6) << 2;

    const int wid = tid >> 5, lane = tid & 31;
    const int wm = (wid >> 1) * 32, wn = (wid & 1) * 32;
    const int r = lane >> 2, cq = lane & 3;

    uint32_t aB0[2], aB1[2], bB0[2], bB1[2];
#pragma unroll
    for (int s = 0; s < 2; s++) {
        aB0[s] = frag_base_m(smA[s], wm,      lane, LDA);
        aB1[s] = frag_base_m(smA[s], wm + 16, lane, LDA);
        bB0[s] = frag_base_n(smB[s], wn,      lane, LDBN);
        bB1[s] = frag_base_n(smB[s], wn + 16, lane, LDBN);
    }

    float acc[2][4][4];
#pragma unroll
    for (int mt = 0; mt < 2; mt++)
#pragma unroll
        for (int nt = 0; nt < 4; nt++)
#pragma unroll
            for (int i = 0; i < 4; i++) acc[mt][nt][i] = 0.f;

    float4 pa[4];
    float  pb[2][4];
    const int nch = K / BK;

    /* prologue: chunk 0 into stage 0 */
#pragma unroll
    for (int p = 0; p < 4; p++)
        pa[p] = *(const float4*)(A + (size_t)(row0 + arow + 32*p)*K + acol);
#pragma unroll
    for (int p = 0; p < 2; p++)
#pragma unroll
        for (int j = 0; j < 4; j++)
            pb[p][j] = W[(size_t)(bk4 + 16*p + j)*N + col0 + bn];
#pragma unroll
    for (int p = 0; p < 4; p++)
        *(float4*)&lsm[(arow + 32*p)*LDA + acol] = cvt4(pa[p]);
#pragma unroll
    for (int p = 0; p < 2; p++) {
        float4 t = make_float4(pb[p][0], pb[p][1], pb[p][2], pb[p][3]);
        *(float4*)&lsm[2*LIN_AS + bn*LDBN + bk4 + 16*p] = cvt4(t);
    }
    __syncthreads();

    for (int c = 0; c < nch; c++) {
        const int cur = c & 1, nxt = cur ^ 1;

        if (c + 1 < nch) {
            int k0 = (c + 1) * BK;
#pragma unroll
            for (int p = 0; p < 4; p++)
                pa[p] = *(const float4*)(A + (size_t)(row0 + arow + 32*p)*K + k0 + acol);
#pragma unroll
            for (int p = 0; p < 2; p++)
#pragma unroll
                for (int j = 0; j < 4; j++)
                    pb[p][j] = W[(size_t)(k0 + bk4 + 16*p + j)*N + col0 + bn];
        }

        MMA_CHUNK(aB0[cur], aB1[cur], bB0[cur], bB1[cur], acc);

        if (c + 1 < nch) {
#pragma unroll
            for (int p = 0; p < 4; p++)
                *(float4*)&lsm[nxt*LIN_AS + (arow + 32*p)*LDA + acol] = cvt4(pa[p]);
#pragma unroll
            for (int p = 0; p < 2; p++) {
                float4 t = make_float4(pb[p][0], pb[p][1], pb[p][2], pb[p][3]);
                *(float4*)&lsm[2*LIN_AS + nxt*LIN_BS + bn*LDBN + bk4 + 16*p] = cvt4(t);
            }
            __syncthreads();
        }
    }

#pragma unroll
    for (int mt = 0; mt < 2; mt++)
#pragma unroll
        for (int nt = 0; nt < 4; nt++) {
            int col = col0 + wn + nt*8 + cq*2;
            float b0 = bias[col], b1 = bias[col + 1];
#pragma unroll
            for (int hrow = 0; hrow < 2; hrow++) {
                int row = row0 + wm + mt*16 + r + hrow*8;
                float v0 = acc[mt][nt][hrow*2 + 0] + b0;
                float v1 = acc[mt][nt][hrow*2 + 1] + b1;
                if (act == 1) {
                    v0 = (v0 > 0.f) ? v0 : 0.2f*v0;
                    v1 = (v1 > 0.f) ? v1 : 0.2f*v1;
                } else if (act == 4) {
                    v0 = tf32r(v0 * 0.125f); v1 = tf32r(v1 * 0.125f);
                } else if (act >= 2) {
                    v0 = tf32r(v0); v1 = tf32r(v1);
                }
                if (act == 3) {
                    int bb = row >> 11, token = row & (SEQ - 1);
                    int h0 = col >> 6, d0 = col & 63;
                    float* dst = C + ((size_t)(bb*NHD + h0)*DK + d0)*SEQ + token;
                    dst[0]   = v0;
                    dst[SEQ] = v1;
                } else {
                    *(float2*)&C[(size_t)row*N + col] = make_float2(v0, v1);
                }
            }
        }
}

/* =================== Flash attention (R7, Q pre-scaled) ================== */
__global__ void __launch_bounds__(256, 2) flash_tc(
    const float* __restrict__ Q, const float* __restrict__ K,
    const float* __restrict__ Vt, const int* __restrict__ mask,
    float* __restrict__ Cv)
{
    extern __shared__ __align__(16) float sm[];
    const uint32_t smBase = smem_u32(sm);
    const uint32_t smQ = smBase + OFF_Q*4u;
    const uint32_t smK[2] = { smBase + OFF_K*4u, smBase + (OFF_K + KT*LDK)*4u };
    const uint32_t smV[2] = { smBase + OFF_V*4u, smBase + (OFF_V + DK*LDV)*4u };
    const uint32_t smM = smBase + OFF_MB*4u;
    const int* MBI = (const int*)(sm + OFF_MB);

    const int bh = blockIdx.y;
    const int b = bh >> 4, h = bh & 15;
    const int i0 = blockIdx.x * 128;
    const float* Qp  = Q  + (size_t)b*SEQ*HID + h*DK;
    const float* Kp  = K  + (size_t)b*SEQ*HID + h*DK;
    const float* Vtp = Vt + (size_t)bh*DK*SEQ;
    const int* mrow = mask + b*SEQ;
    float* Cp = Cv + (size_t)b*SEQ*HID + h*DK;

    const int tid = threadIdx.x;
    const int wid = tid >> 5, lane = tid & 31;
    const int wm = wid * 16;
    const int r = lane >> 2, cq = lane & 3;

#pragma unroll
    for (int p = 0; p < 8; p++) {
        int idx = p*256 + tid;
        int row = idx >> 4, u = idx & 15;
        cpa16(smQ + (uint32_t)(row*LDQ + u*4)*4u,
              Qp + (size_t)(i0 + row)*HID + u*4);
    }
#pragma unroll
    for (int p = 0; p < 2; p++) {
        int idx = p*256 + tid;
        int krow = idx >> 4, ku = idx & 15;
        cpa16(smK[0] + (uint32_t)(krow*LDK + ku*4)*4u,
              Kp + (size_t)krow*HID + ku*4);
        int vrow = idx >> 3, vu = idx & 7;
        cpa16(smV[0] + (uint32_t)(vrow*LDV + vu*4)*4u,
              Vtp + (size_t)vrow*SEQ + vu*4);
    }
    if (tid < 8) cpa16(smM + (uint32_t)(tid*4)*4u, mrow + tid*4);
    CPA_COMMIT();

    const uint32_t aQ = frag_base_m(smQ, wm, lane, LDQ);
    const uint32_t aP = frag_base_m(smBase + OFF_P*4u, wm, lane, LDP);
    uint32_t bKf[2][2], bVf[2][4];
#pragma unroll
    for (int buf = 0; buf < 2; buf++) {
#pragma unroll
        for (int g = 0; g < 2; g++) bKf[buf][g] = frag_base_n(smK[buf], g*16, lane, LDK);
#pragma unroll
        for (int g = 0; g < 4; g++) bVf[buf][g] = frag_base_n(smV[buf], g*16, lane, LDV);
    }

    float acc_o[8][4];
#pragma unroll
    for (int nt = 0; nt < 8; nt++)
#pragma unroll
        for (int i = 0; i < 4; i++) acc_o[nt][i] = 0.f;
    float m_st[2] = {-1e20f, -1e20f};
    float l_st[2] = {0.f, 0.f};

    for (int c = 0; c < NCH; c++) {
        const int cur = c & 1, nxt = cur ^ 1;

        CPA_WAIT0();
        __syncthreads();

        if (c + 1 < NCH) {
            const size_t k0 = (size_t)(c + 1) * KT;
#pragma unroll
            for (int p = 0; p < 2; p++) {
                int idx = p*256 + tid;
                int krow = idx >> 4, ku = idx & 15;
                cpa16(smK[nxt] + (uint32_t)(krow*LDK + ku*4)*4u,
                      Kp + (k0 + krow)*HID + ku*4);
                int vrow = idx >> 3, vu = idx & 7;
                cpa16(smV[nxt] + (uint32_t)(vrow*LDV + vu*4)*4u,
                      Vtp + (size_t)vrow*SEQ + k0 + vu*4);
            }
            if (tid < 8) cpa16(smM + (uint32_t)(nxt*KT + tid*4)*4u, mrow + k0 + tid*4);
            CPA_COMMIT();
        }

        float acc_s[4][4];
#pragma unroll
        for (int nt = 0; nt < 4; nt++)
#pragma unroll
            for (int i = 0; i < 4; i++) acc_s[nt][i] = 0.f;
#pragma unroll
        for (int kk = 0; kk < DK; kk += 8) {
            uint32_t af[4];
            ldsm4(af, aQ + kk*4);
#pragma unroll
            for (int g = 0; g < 2; g++) {
                uint32_t bq[4];
                ldsm4(bq, bKf[cur][g] + kk*4);
                mma_tf32(acc_s[2*g    ], af, &bq[0]);
                mma_tf32(acc_s[2*g + 1], af, &bq[2]);
            }
        }

        const int* mi = MBI + cur*KT;
        float bias2[4][2];
#pragma unroll
        for (int nt = 0; nt < 4; nt++) {
            int j = nt*8 + cq*2;
            bias2[nt][0] = mi[j]     ? 0.f : -1e20f;
            bias2[nt][1] = mi[j + 1] ? 0.f : -1e20f;
        }
        float alpha[2];
#pragma unroll
        for (int rr = 0; rr < 2; rr++) {
            float mx = -3.4e38f;
#pragma unroll
            for (int nt = 0; nt < 4; nt++)
#pragma unroll
                for (int cc = 0; cc < 2; cc++) {
                    float s = acc_s[nt][rr*2+cc] + bias2[nt][cc];   /* Q pre-scaled */
                    acc_s[nt][rr*2+cc] = s;
                    mx = fmaxf(mx, s);
                }
            mx = fmaxf(mx, __shfl_xor_sync(0xffffffffu, mx, 1));
            mx = fmaxf(mx, __shfl_xor_sync(0xffffffffu, mx, 2));
            float m_new = fmaxf(m_st[rr], mx);
            float a = __expf(m_st[rr] - m_new);
            m_st[rr] = m_new;
            alpha[rr] = a;
            float lsum = 0.f;
#pragma unroll
            for (int nt = 0; nt < 4; nt++)
#pragma unroll
                for (int cc = 0; cc < 2; cc++) {
                    float p = __expf(acc_s[nt][rr*2+cc] - m_new);
                    acc_s[nt][rr*2+cc] = p;
                    lsum += p;
                }
            l_st[rr] = l_st[rr]*a + lsum;
        }
#pragma unroll
        for (int nt = 0; nt < 8; nt++)
#pragma unroll
            for (int i = 0; i < 4; i++) acc_o[nt][i] *= alpha[i>>1];

#pragma unroll
        for (int rr = 0; rr < 2; rr++) {
            int prow = wm + rr*8 + r;
#pragma unroll
            for (int nt = 0; nt < 4; nt++)
                *(float2*)&sm[OFF_P + prow*LDP + nt*8 + cq*2] =
                    make_float2(tf32r(acc_s[nt][rr*2+0]), tf32r(acc_s[nt][rr*2+1]));
        }
        __syncwarp();

#pragma unroll
        for (int kk = 0; kk < KT; kk += 8) {
            uint32_t af[4];
            ldsm4(af, aP + kk*4);
#pragma unroll
            for (int g = 0; g < 4; g++) {
                uint32_t bv[4];
                ldsm4(bv, bVf[cur][g] + kk*4);
                mma_tf32(acc_o[2*g    ], af, &bv[0]);
                mma_tf32(acc_o[2*g + 1], af, &bv[2]);
            }
        }
    }

    float inv2[2];
#pragma unroll
    for (int rr = 0; rr < 2; rr++) {
        float lt = l_st[rr];
        lt += __shfl_xor_sync(0xffffffffu, lt, 1);
        lt += __shfl_xor_sync(0xffffffffu, lt, 2);
        inv2[rr] = 1.f / lt;
    }
#pragma unroll
    for (int nt = 0; nt < 8; nt++) {
        int col = nt*8 + cq*2;
#pragma unroll
        for (int rr = 0; rr < 2; rr++) {
            int row = i0 + wm + rr*8 + r;
            *(float2*)&Cp[(size_t)row*HID + col] =
                make_float2(acc_o[nt][rr*2+0]*inv2[rr],
                            acc_o[nt][rr*2+1]*inv2[rr]);
        }
    }
}

/* ---------------- host orchestration ------------------------------------- */
extern "C" void kernel_launch(void* const* d_in, const int* in_sizes, int n_in,
                              void* d_out, int out_size)
{
    const float* query = (const float*)d_in[0];
    const float* key   = (const float*)d_in[1];
    const float* value = (const float*)d_in[2];
    const int*   mask  = (const int*)  d_in[3];
    const float* Wpq = (const float*)d_in[4],  *bpq = (const float*)d_in[5];
    const float* Wtq = (const float*)d_in[6],  *btq = (const float*)d_in[7];
    const float* Wpk = (const float*)d_in[8],  *bpk = (const float*)d_in[9];
    const float* Wtk = (const float*)d_in[10], *btk = (const float*)d_in[11];
    const float* Wpv = (const float*)d_in[12], *bpv = (const float*)d_in[13];
    const float* Wtv = (const float*)d_in[14], *btv = (const float*)d_in[15];
    const float* Wpo = (const float*)d_in[16], *bpo = (const float*)d_in[17];
    const float* Wto = (const float*)d_in[18], *bto = (const float*)d_in[19];
    float* out = (float*)d_out;

    float *q_, *k_, *vt_, *h_, *cv_;
    cudaGetSymbolAddress((void**)&q_,  g_q);
    cudaGetSymbolAddress((void**)&k_,  g_k);
    cudaGetSymbolAddress((void**)&vt_, g_vt);
    cudaGetSymbolAddress((void**)&h_,  g_h);
    cudaGetSymbolAddress((void**)&cv_, g_cv);

    cudaFuncSetAttribute(flash_tc, cudaFuncAttributeMaxDynamicSharedMemorySize,
                         FLASH_SMEM);
    cudaFuncSetAttribute(linear_tc, cudaFuncAttributeMaxDynamicSharedMemorySize,
                         LIN_SMEM);

    dim3 blk(256);
    dim3 gproj(ROWS/BM, FAC/BN);   /* (64, 4)  */
    dim3 gtran(ROWS/BM, HID/BN);   /* (64, 16) */

    linear_tc<<<gproj, blk, LIN_SMEM>>>(query, Wpq, bpq, h_, ROWS, FAC, HID, 1);
    linear_tc<<<gtran, blk, LIN_SMEM>>>(h_,    Wtq, btq, q_, ROWS, HID, FAC, 4);
    linear_tc<<<gproj, blk, LIN_SMEM>>>(key,   Wpk, bpk, h_, ROWS, FAC, HID, 1);
    linear_tc<<<gtran, blk, LIN_SMEM>>>(h_,    Wtk, btk, k_, ROWS, HID, FAC, 2);
    linear_tc<<<gproj, blk, LIN_SMEM>>>(value, Wpv, bpv, h_, ROWS, FAC, HID, 1);
    linear_tc<<<gtran, blk, LIN_SMEM>>>(h_,    Wtv, btv, vt_, ROWS, HID, FAC, 3);

    flash_tc<<<dim3(SEQ/128, BH), blk, FLASH_SMEM>>>(q_, k_, vt_, mask, cv_);

    linear_tc<<<gproj, blk, LIN_SMEM>>>(cv_, Wpo, bpo, h_,  ROWS, FAC, HID, 1);
    linear_tc<<<gtran, blk, LIN_SMEM>>>(h_,  Wto, bto, out, ROWS, HID, FAC, 0);
}

// round 13
// speedup vs baseline: 1.0978x; 1.0978x over previous
#include <cuda_runtime.h>
#include <math.h>
#include <stdint.h>

#define NB   4
#define SEQ  2048
#define HID  1024
#define FAC  256
#define NHD  16
#define DK   64
#define ROWS (NB*SEQ)   /* 8192 */
#define BH   (NB*NHD)   /* 64   */

/* linear tiling: 128x64 block, 8 warps of 32x32 (R7 geometry, FROZEN) */
#define BM 128
#define BN 64
#define BK 32
#define LDA  36
#define LDBN 36

/* flash geometry (R7, FROZEN) */
#define KT   32
#define NCH  (SEQ/KT)    /* 64 */
#define LDQ  68
#define LDK  68
#define LDV  36
#define LDP  36
#define OFF_Q   0
#define OFF_K   (128*LDQ)                 /* 8704  */
#define OFF_V   (OFF_K + 2*KT*LDK)        /* 13056 */
#define OFF_P   (OFF_V + 2*DK*LDV)        /* 17664 */
#define OFF_MB  (OFF_P + 128*LDP)         /* 22272 */
#define FLASH_FLOATS (OFF_MB + 2*KT)      /* 22336 */
#define FLASH_SMEM   (FLASH_FLOATS*4)     /* 89344 B */

/* 0.125 * log2(e): Q prescale so scores land in the log2 domain */
#define QSCALE 0.1803368801111204f

/* ---------------- scratch ------------------------------------------------ */
__device__ float g_q  [ROWS*HID];
__device__ float g_k  [ROWS*HID];
__device__ float g_vt [BH*DK*SEQ];   /* V transposed: [bh][d][token] */
__device__ float g_h  [ROWS*FAC];
__device__ float g_cv [ROWS*HID];

/* ---------------- helpers ------------------------------------------------ */
__device__ __forceinline__ float tf32r(float x) {
    uint32_t u;
    asm("cvt.rna.tf32.f32 %0, %1;" : "=r"(u) : "f"(x));
    return __uint_as_float(u);
}
__device__ __forceinline__ float4 cvt4(float4 v) {
    v.x = tf32r(v.x); v.y = tf32r(v.y); v.z = tf32r(v.z); v.w = tf32r(v.w);
    return v;
}
__device__ __forceinline__ float ex2(float x) {
    float y;
    asm("ex2.approx.f32 %0, %1;" : "=f"(y) : "f"(x));
    return y;
}
__device__ __forceinline__ void mma_tf32(float c[4], const uint32_t a[4], const uint32_t b[2]) {
    asm volatile(
        "mma.sync.aligned.m16n8k8.row.col.f32.tf32.tf32.f32 "
        "{%0,%1,%2,%3}, {%4,%5,%6,%7}, {%8,%9}, {%0,%1,%2,%3};"
        : "+f"(c[0]), "+f"(c[1]), "+f"(c[2]), "+f"(c[3])
        : "r"(a[0]), "r"(a[1]), "r"(a[2]), "r"(a[3]), "r"(b[0]), "r"(b[1]));
}
__device__ __forceinline__ void ldsm4(uint32_t f[4], uint32_t addr) {
    asm volatile("ldmatrix.sync.aligned.m8n8.x4.shared.b16 {%0,%1,%2,%3}, [%4];"
        : "=r"(f[0]), "=r"(f[1]), "=r"(f[2]), "=r"(f[3]) : "r"(addr));
}
__device__ __forceinline__ uint32_t smem_u32(const void* p) {
    return (uint32_t)__cvta_generic_to_shared(p);
}
__device__ __forceinline__ void cpa16(uint32_t dst, const void* src) {
    asm volatile("cp.async.cg.shared.global [%0], [%1], 16;" :: "r"(dst), "l"(src));
}
#define CPA_COMMIT() asm volatile("cp.async.commit_group;" ::: "memory")
#define CPA_WAIT0()  asm volatile("cp.async.wait_group 0;" ::: "memory")

__device__ __forceinline__ uint32_t frag_base_m(uint32_t base, int row0, int lane, int ld) {
    int lr = lane & 7, sel = lane >> 3;
    int row = row0 + lr + ((sel & 1) << 3);
    int col = (sel & 2) << 1;
    return base + (uint32_t)(row*ld + col)*4u;
}
__device__ __forceinline__ uint32_t frag_base_n(uint32_t base, int n0, int lane, int ld) {
    int lr = lane & 7, sel = lane >> 3;
    int row = n0 + lr + ((sel & 2) << 2);
    int col = (sel & 1) << 2;
    return base + (uint32_t)(row*ld + col)*4u;
}

#define MMA_CHUNK(aB0, aB1, bB0, bB1, acc)                                    \
    _Pragma("unroll")                                                         \
    for (int kk = 0; kk < BK; kk += 8) {                                      \
        uint32_t af0[4], af1[4], bq0[4], bq1[4];                              \
        ldsm4(af0, (aB0) + kk*4);                                             \
        ldsm4(af1, (aB1) + kk*4);                                             \
        ldsm4(bq0, (bB0) + kk*4);                                             \
        ldsm4(bq1, (bB1) + kk*4);                                             \
        mma_tf32(acc[0][0], af0, &bq0[0]);                                    \
        mma_tf32(acc[0][1], af0, &bq0[2]);                                    \
        mma_tf32(acc[0][2], af0, &bq1[0]);                                    \
        mma_tf32(acc[0][3], af0, &bq1[2]);                                    \
        mma_tf32(acc[1][0], af1, &bq0[0]);                                    \
        mma_tf32(acc[1][1], af1, &bq0[2]);                                    \
        mma_tf32(acc[1][2], af1, &bq1[0]);                                    \
        mma_tf32(acc[1][3], af1, &bq1[2]);                                    \
    }

/* =================== TF32 linear (R7 body, FROZEN) =======================
   act: 0 = bias; 1 = bias+leaky(0.2); 2 = bias+tf32 round;
        3 = bias+tf32 round + TRANSPOSED store into Vt[bh][d][token];
        4 = bias, *QSCALE, tf32 round (Q prescale, log2 domain)            */
__global__ void __launch_bounds__(256) linear_tc(
    const float* __restrict__ A, const float* __restrict__ W,
    const float* __restrict__ bias, float* __restrict__ C,
    int M, int N, int K, int act)
{
    __shared__ __align__(16) float As[BM][LDA];
    __shared__ __align__(16) float Bs[BN][LDBN];

    const int tid = threadIdx.x;
    const int row0 = blockIdx.x * BM;
    const int col0 = blockIdx.y * BN;

    const int arow = tid >> 3, acol = (tid & 7) << 2;
    const int bn = tid & 63, bk4 = (tid >> 6) << 2;

    const int wid = tid >> 5, lane = tid & 31;
    const int wm = (wid >> 1) * 32, wn = (wid & 1) * 32;
    const int r = lane >> 2, cq = lane & 3;

    const uint32_t smA = smem_u32(&As[0][0]);
    const uint32_t smB = smem_u32(&Bs[0][0]);
    const uint32_t aB0 = frag_base_m(smA, wm,      lane, LDA);
    const uint32_t aB1 = frag_base_m(smA, wm + 16, lane, LDA);
    const uint32_t bB0 = frag_base_n(smB, wn,      lane, LDBN);
    const uint32_t bB1 = frag_base_n(smB, wn + 16, lane, LDBN);

    float acc[2][4][4];
#pragma unroll
    for (int mt = 0; mt < 2; mt++)
#pragma unroll
        for (int nt = 0; nt < 4; nt++)
#pragma unroll
            for (int i = 0; i < 4; i++) acc[mt][nt][i] = 0.f;

    float4 pa[4];
    float  pb[2][4];
    const int nch = K / BK;

#pragma unroll
    for (int p = 0; p < 4; p++)
        pa[p] = *(const float4*)(A + (size_t)(row0 + arow + 32*p)*K + acol);
#pragma unroll
    for (int p = 0; p < 2; p++)
#pragma unroll
        for (int j = 0; j < 4; j++)
            pb[p][j] = W[(size_t)(bk4 + 16*p + j)*N + col0 + bn];

    for (int c = 0; c < nch; c++) {
#pragma unroll
        for (int p = 0; p < 4; p++)
            *(float4*)&As[arow + 32*p][acol] = cvt4(pa[p]);
#pragma unroll
        for (int p = 0; p < 2; p++) {
            float4 t = make_float4(pb[p][0], pb[p][1], pb[p][2], pb[p][3]);
            *(float4*)&Bs[bn][bk4 + 16*p] = cvt4(t);
        }
        __syncthreads();

        if (c + 1 < nch) {
            int k0 = (c + 1) * BK;
#pragma unroll
            for (int p = 0; p < 4; p++)
                pa[p] = *(const float4*)(A + (size_t)(row0 + arow + 32*p)*K + k0 + acol);
#pragma unroll
            for (int p = 0; p < 2; p++)
#pragma unroll
                for (int j = 0; j < 4; j++)
                    pb[p][j] = W[(size_t)(k0 + bk4 + 16*p + j)*N + col0 + bn];
        }

        MMA_CHUNK(aB0, aB1, bB0, bB1, acc);
        __syncthreads();
    }

#pragma unroll
    for (int mt = 0; mt < 2; mt++)
#pragma unroll
        for (int nt = 0; nt < 4; nt++) {
            int col = col0 + wn + nt*8 + cq*2;
            float b0 = bias[col], b1 = bias[col + 1];
#pragma unroll
            for (int hrow = 0; hrow < 2; hrow++) {
                int row = row0 + wm + mt*16 + r + hrow*8;
                float v0 = acc[mt][nt][hrow*2 + 0] + b0;
                float v1 = acc[mt][nt][hrow*2 + 1] + b1;
                if (act == 1) {
                    v0 = (v0 > 0.f) ? v0 : 0.2f*v0;
                    v1 = (v1 > 0.f) ? v1 : 0.2f*v1;
                } else if (act == 4) {
                    v0 = tf32r(v0 * QSCALE); v1 = tf32r(v1 * QSCALE);
                } else if (act >= 2) {
                    v0 = tf32r(v0); v1 = tf32r(v1);
                }
                if (act == 3) {
                    int bb = row >> 11, token = row & (SEQ - 1);
                    int h0 = col >> 6, d0 = col & 63;
                    float* dst = C + ((size_t)(bb*NHD + h0)*DK + d0)*SEQ + token;
                    dst[0]   = v0;
                    dst[SEQ] = v1;
                } else {
                    *(float2*)&C[(size_t)row*N + col] = make_float2(v0, v1);
                }
            }
        }
}

/* =================== Flash attention (R7 body, base-2 softmax) =========== */
__global__ void __launch_bounds__(256, 2) flash_tc(
    const float* __restrict__ Q, const float* __restrict__ K,
    const float* __restrict__ Vt, const int* __restrict__ mask,
    float* __restrict__ Cv)
{
    extern __shared__ __align__(16) float sm[];
    const uint32_t smBase = smem_u32(sm);
    const uint32_t smQ = smBase + OFF_Q*4u;
    const uint32_t smK[2] = { smBase + OFF_K*4u, smBase + (OFF_K + KT*LDK)*4u };
    const uint32_t smV[2] = { smBase + OFF_V*4u, smBase + (OFF_V + DK*LDV)*4u };
    const uint32_t smM = smBase + OFF_MB*4u;
    const int* MBI = (const int*)(sm + OFF_MB);

    const int bh = blockIdx.y;
    const int b = bh >> 4, h = bh & 15;
    const int i0 = blockIdx.x * 128;
    const float* Qp  = Q  + (size_t)b*SEQ*HID + h*DK;
    const float* Kp  = K  + (size_t)b*SEQ*HID + h*DK;
    const float* Vtp = Vt + (size_t)bh*DK*SEQ;
    const int* mrow = mask + b*SEQ;
    float* Cp = Cv + (size_t)b*SEQ*HID + h*DK;

    const int tid = threadIdx.x;
    const int wid = tid >> 5, lane = tid & 31;
    const int wm = wid * 16;
    const int r = lane >> 2, cq = lane & 3;

#pragma unroll
    for (int p = 0; p < 8; p++) {
        int idx = p*256 + tid;
        int row = idx >> 4, u = idx & 15;
        cpa16(smQ + (uint32_t)(row*LDQ + u*4)*4u,
              Qp + (size_t)(i0 + row)*HID + u*4);
    }
#pragma unroll
    for (int p = 0; p < 2; p++) {
        int idx = p*256 + tid;
        int krow = idx >> 4, ku = idx & 15;
        cpa16(smK[0] + (uint32_t)(krow*LDK + ku*4)*4u,
              Kp + (size_t)krow*HID + ku*4);
        int vrow = idx >> 3, vu = idx & 7;
        cpa16(smV[0] + (uint32_t)(vrow*LDV + vu*4)*4u,
              Vtp + (size_t)vrow*SEQ + vu*4);
    }
    if (tid < 8) cpa16(smM + (uint32_t)(tid*4)*4u, mrow + tid*4);
    CPA_COMMIT();

    const uint32_t aQ = frag_base_m(smQ, wm, lane, LDQ);
    const uint32_t aP = frag_base_m(smBase + OFF_P*4u, wm, lane, LDP);
    uint32_t bKf[2][2], bVf[2][4];
#pragma unroll
    for (int buf = 0; buf < 2; buf++) {
#pragma unroll
        for (int g = 0; g < 2; g++) bKf[buf][g] = frag_base_n(smK[buf], g*16, lane, LDK);
#pragma unroll
        for (int g = 0; g < 4; g++) bVf[buf][g] = frag_base_n(smV[buf], g*16, lane, LDV);
    }

    float acc_o[8][4];
#pragma unroll
    for (int nt = 0; nt < 8; nt++)
#pragma unroll
        for (int i = 0; i < 4; i++) acc_o[nt][i] = 0.f;
    float m_st[2] = {-1e20f, -1e20f};
    float l_st[2] = {0.f, 0.f};

    for (int c = 0; c < NCH; c++) {
        const int cur = c & 1, nxt = cur ^ 1;

        CPA_WAIT0();
        __syncthreads();

        if (c + 1 < NCH) {
            const size_t k0 = (size_t)(c + 1) * KT;
#pragma unroll
            for (int p = 0; p < 2; p++) {
                int idx = p*256 + tid;
                int krow = idx >> 4, ku = idx & 15;
                cpa16(smK[nxt] + (uint32_t)(krow*LDK + ku*4)*4u,
                      Kp + (k0 + krow)*HID + ku*4);
                int vrow = idx >> 3, vu = idx & 7;
                cpa16(smV[nxt] + (uint32_t)(vrow*LDV + vu*4)*4u,
                      Vtp + (size_t)vrow*SEQ + k0 + vu*4);
            }
            if (tid < 8) cpa16(smM + (uint32_t)(nxt*KT + tid*4)*4u, mrow + k0 + tid*4);
            CPA_COMMIT();
        }

        float acc_s[4][4];
#pragma unroll
        for (int nt = 0; nt < 4; nt++)
#pragma unroll
            for (int i = 0; i < 4; i++) acc_s[nt][i] = 0.f;
#pragma unroll
        for (int kk = 0; kk < DK; kk += 8) {
            uint32_t af[4];
            ldsm4(af, aQ + kk*4);
#pragma unroll
            for (int g = 0; g < 2; g++) {
                uint32_t bq[4];
                ldsm4(bq, bKf[cur][g] + kk*4);
                mma_tf32(acc_s[2*g    ], af, &bq[0]);
                mma_tf32(acc_s[2*g + 1], af, &bq[2]);
            }
        }

        /* base-2 online softmax: scores already in log2 domain (Q prescaled) */
        const int* mi = MBI + cur*KT;
        float bias2[4][2];
#pragma unroll
        for (int nt = 0; nt < 4; nt++) {
            int j = nt*8 + cq*2;
            bias2[nt][0] = mi[j]     ? 0.f : -1e20f;
            bias2[nt][1] = mi[j + 1] ? 0.f : -1e20f;
        }
        float alpha[2];
#pragma unroll
        for (int rr = 0; rr < 2; rr++) {
            float mx = -3.4e38f;
#pragma unroll
            for (int nt = 0; nt < 4; nt++)
#pragma unroll
                for (int cc = 0; cc < 2; cc++) {
                    float s = acc_s[nt][rr*2+cc] + bias2[nt][cc];
                    acc_s[nt][rr*2+cc] = s;
                    mx = fmaxf(mx, s);
                }
            mx = fmaxf(mx, __shfl_xor_sync(0xffffffffu, mx, 1));
            mx = fmaxf(mx, __shfl_xor_sync(0xffffffffu, mx, 2));
            float m_new = fmaxf(m_st[rr], mx);
            float a = ex2(m_st[rr] - m_new);
            m_st[rr] = m_new;
            alpha[rr] = a;
            float lsum = 0.f;
#pragma unroll
            for (int nt = 0; nt < 4; nt++)
#pragma unroll
                for (int cc = 0; cc < 2; cc++) {
                    float p = ex2(acc_s[nt][rr*2+cc] - m_new);
                    acc_s[nt][rr*2+cc] = p;
                    lsum += p;
                }
            l_st[rr] = l_st[rr]*a + lsum;
        }
#pragma unroll
        for (int nt = 0; nt < 8; nt++)
#pragma unroll
            for (int i = 0; i < 4; i++) acc_o[nt][i] *= alpha[i>>1];

#pragma unroll
        for (int rr = 0; rr < 2; rr++) {
            int prow = wm + rr*8 + r;
#pragma unroll
            for (int nt = 0; nt < 4; nt++)
                *(float2*)&sm[OFF_P + prow*LDP + nt*8 + cq*2] =
                    make_float2(tf32r(acc_s[nt][rr*2+0]), tf32r(acc_s[nt][rr*2+1]));
        }
        __syncwarp();

#pragma unroll
        for (int kk = 0; kk < KT; kk += 8) {
            uint32_t af[4];
            ldsm4(af, aP + kk*4);
#pragma unroll
            for (int g = 0; g < 4; g++) {
                uint32_t bv[4];
                ldsm4(bv, bVf[cur][g] + kk*4);
                mma_tf32(acc_o[2*g    ], af, &bv[0]);
                mma_tf32(acc_o[2*g + 1], af, &bv[2]);
            }
        }
    }

    float inv2[2];
#pragma unroll
    for (int rr = 0; rr < 2; rr++) {
        float lt = l_st[rr];
        lt += __shfl_xor_sync(0xffffffffu, lt, 1);
        lt += __shfl_xor_sync(0xffffffffu, lt, 2);
        inv2[rr] = 1.f / lt;
    }
#pragma unroll
    for (int nt = 0; nt < 8; nt++) {
        int col = nt*8 + cq*2;
#pragma unroll
        for (int rr = 0; rr < 2; rr++) {
            int row = i0 + wm + rr*8 + r;
            *(float2*)&Cp[(size_t)row*HID + col] =
                make_float2(acc_o[nt][rr*2+0]*inv2[rr],
                            acc_o[nt][rr*2+1]*inv2[rr]);
        }
    }
}

/* ---------------- host orchestration ------------------------------------- */
extern "C" void kernel_launch(void* const* d_in, const int* in_sizes, int n_in,
                              void* d_out, int out_size)
{
    const float* query = (const float*)d_in[0];
    const float* key   = (const float*)d_in[1];
    const float* value = (const float*)d_in[2];
    const int*   mask  = (const int*)  d_in[3];
    const float* Wpq = (const float*)d_in[4],  *bpq = (const float*)d_in[5];
    const float* Wtq = (const float*)d_in[6],  *btq = (const float*)d_in[7];
    const float* Wpk = (const float*)d_in[8],  *bpk = (const float*)d_in[9];
    const float* Wtk = (const float*)d_in[10], *btk = (const float*)d_in[11];
    const float* Wpv = (const float*)d_in[12], *bpv = (const float*)d_in[13];
    const float* Wtv = (const float*)d_in[14], *btv = (const float*)d_in[15];
    const float* Wpo = (const float*)d_in[16], *bpo = (const float*)d_in[17];
    const float* Wto = (const float*)d_in[18], *bto = (const float*)d_in[19];
    float* out = (float*)d_out;

    float *q_, *k_, *vt_, *h_, *cv_;
    cudaGetSymbolAddress((void**)&q_,  g_q);
    cudaGetSymbolAddress((void**)&k_,  g_k);
    cudaGetSymbolAddress((void**)&vt_, g_vt);
    cudaGetSymbolAddress((void**)&h_,  g_h);
    cudaGetSymbolAddress((void**)&cv_, g_cv);

    cudaFuncSetAttribute(flash_tc, cudaFuncAttributeMaxDynamicSharedMemorySize,
                         FLASH_SMEM);

    dim3 blk(256);
    dim3 gproj(ROWS/BM, FAC/BN);   /* (64, 4)  */
    dim3 gtran(ROWS/BM, HID/BN);   /* (64, 16) */

    linear_tc<<<gproj, blk>>>(query, Wpq, bpq, h_, ROWS, FAC, HID, 1);
    linear_tc<<<gtran, blk>>>(h_,    Wtq, btq, q_, ROWS, HID, FAC, 4);
    linear_tc<<<gproj, blk>>>(key,   Wpk, bpk, h_, ROWS, FAC, HID, 1);
    linear_tc<<<gtran, blk>>>(h_,    Wtk, btk, k_, ROWS, HID, FAC, 2);
    linear_tc<<<gproj, blk>>>(value, Wpv, bpv, h_, ROWS, FAC, HID, 1);
    linear_tc<<<gtran, blk>>>(h_,    Wtv, btv, vt_, ROWS, HID, FAC, 3);

    flash_tc<<<dim3(SEQ/128, BH), blk, FLASH_SMEM>>>(q_, k_, vt_, mask, cv_);

    linear_tc<<<gproj, blk>>>(cv_, Wpo, bpo, h_,  ROWS, FAC, HID, 1);
    linear_tc<<<gtran, blk>>>(h_,  Wto, bto, out, ROWS, HID, FAC, 0);
}

// round 14
// speedup vs baseline: 1.6101x; 1.4667x over previous
#include <cuda_runtime.h>
#include <cuda_fp16.h>
#include <math.h>
#include <stdint.h>

#define NB   4
#define SEQ  2048
#define HID  1024
#define FAC  256
#define NHD  16
#define DK   64
#define ROWS (NB*SEQ)   /* 8192 */
#define BH   (NB*NHD)   /* 64   */

/* linear tiling: 128x64 block, 8 warps of 32x32, fp16 operands */
#define BM 128
#define BN 64
#define BK 32
#define LDA_H 40   /* halves; 80B row stride, 16B-aligned, conflict-free */
#define LDB_H 40

/* flash geometry: fp16 operands */
#define KT   32
#define NCH  (SEQ/KT)    /* 64 */
#define LDQH 72          /* 144B rows */
#define LDKH 72
#define LDVH 40
#define LDPH 40
#define HOFF_Q  0
#define HOFF_K  (128*LDQH)              /* 9216  */
#define HOFF_V  (HOFF_K + 2*KT*LDKH)    /* 13824 */
#define HOFF_P  (HOFF_V + 2*DK*LDVH)    /* 18944 */
#define HOFF_MB (HOFF_P + 128*LDPH)     /* 24064 halves -> 48128 B, 4B aligned */
#define FLASH_SMEM (HOFF_MB*2 + 2*KT*4) /* 48384 B */

/* 0.125 * log2(e): Q prescale so scores land in the log2 domain */
#define QSCALE 0.1803368801111204f

/* ---------------- scratch ------------------------------------------------ */
__device__ __half g_q  [ROWS*HID];
__device__ __half g_k  [ROWS*HID];
__device__ __half g_vt [BH*DK*SEQ];   /* V transposed: [bh][d][token] */
__device__ __half g_h  [ROWS*FAC];
__device__ __half g_cv [ROWS*HID];

/* ---------------- helpers ------------------------------------------------ */
__device__ __forceinline__ uint32_t h2pack(float a, float b) {
    __half2 h = __floats2half2_rn(a, b);
    return *(uint32_t*)&h;
}
__device__ __forceinline__ float ex2(float x) {
    float y;
    asm("ex2.approx.f32 %0, %1;" : "=f"(y) : "f"(x));
    return y;
}
__device__ __forceinline__ void mma_f16(float c[4], const uint32_t a[4], const uint32_t b[2]) {
    asm volatile(
        "mma.sync.aligned.m16n8k16.row.col.f32.f16.f16.f32 "
        "{%0,%1,%2,%3}, {%4,%5,%6,%7}, {%8,%9}, {%0,%1,%2,%3};"
        : "+f"(c[0]), "+f"(c[1]), "+f"(c[2]), "+f"(c[3])
        : "r"(a[0]), "r"(a[1]), "r"(a[2]), "r"(a[3]), "r"(b[0]), "r"(b[1]));
}
__device__ __forceinline__ void ldsm4(uint32_t f[4], uint32_t addr) {
    asm volatile("ldmatrix.sync.aligned.m8n8.x4.shared.b16 {%0,%1,%2,%3}, [%4];"
        : "=r"(f[0]), "=r"(f[1]), "=r"(f[2]), "=r"(f[3]) : "r"(addr));
}
__device__ __forceinline__ uint32_t smem_u32(const void* p) {
    return (uint32_t)__cvta_generic_to_shared(p);
}
__device__ __forceinline__ void cpa16(uint32_t dst, const void* src) {
    asm volatile("cp.async.cg.shared.global [%0], [%1], 16;" :: "r"(dst), "l"(src));
}
#define CPA_COMMIT() asm volatile("cp.async.commit_group;" ::: "memory")
#define CPA_WAIT0()  asm volatile("cp.async.wait_group 0;" ::: "memory")

/* fp16 A-fragment base (m-major, 16x16 per ldsm.x4): regs a0..a3 match mma A */
__device__ __forceinline__ uint32_t fb_m_h(uint32_t base, int row0, int lane, int ldh) {
    int lr = lane & 7, sel = lane >> 3;
    int row = row0 + lr + ((sel & 1) << 3);
    int colb = (sel & 2) * 8;                 /* 0 or 16 bytes (8 halves) */
    return base + (uint32_t)(row*ldh)*2u + colb;
}
/* fp16 B-fragment base (n-major, covers 2 n-subtiles x k16): r0,r1=b(n0); r2,r3=b(n0+8) */
__device__ __forceinline__ uint32_t fb_n_h(uint32_t base, int n0, int lane, int ldh) {
    int lr = lane & 7, sel = lane >> 3;
    int row = n0 + lr + ((sel & 2) << 2);
    int colb = (sel & 1) * 16;
    return base + (uint32_t)(row*ldh)*2u + colb;
}

/* =================== fp16 linear: C = act(A[M,K]@W[K,N]+b) ===============
   A in gmem fp32 (aHalf=0) or fp16 (aHalf=1); W fp32 (rounded on STS).
   act: 0 = bias, fp32 out; 1 = bias+leaky(0.2), half out;
        2 = bias, half out; 3 = bias, half TRANSPOSED into Vt[bh][d][token];
        4 = bias*QSCALE, half out (Q, log2 domain)                          */
__global__ void __launch_bounds__(256) linear_tc(
    const void* __restrict__ Av, const float* __restrict__ W,
    const float* __restrict__ bias, void* __restrict__ Cv,
    int M, int N, int K, int act, int aHalf)
{
    __shared__ __align__(16) __half As[BM][LDA_H];
    __shared__ __align__(16) __half Bs[BN][LDB_H];

    const int tid = threadIdx.x;
    const int row0 = blockIdx.x * BM;
    const int col0 = blockIdx.y * BN;

    const int arow = tid >> 3, acol4 = (tid & 7) << 2;   /* 4 halves per thread */
    const int bn = tid & 63, bk4 = (tid >> 6) << 2;

    const int wid = tid >> 5, lane = tid & 31;
    const int wm = (wid >> 1) * 32, wn = (wid & 1) * 32;
    const int r = lane >> 2, cq = lane & 3;

    const uint32_t smA = smem_u32(&As[0][0]);
    const uint32_t smB = smem_u32(&Bs[0][0]);
    const uint32_t aB0 = fb_m_h(smA, wm,      lane, LDA_H);
    const uint32_t aB1 = fb_m_h(smA, wm + 16, lane, LDA_H);
    const uint32_t bB0 = fb_n_h(smB, wn,      lane, LDB_H);
    const uint32_t bB1 = fb_n_h(smB, wn + 16, lane, LDB_H);

    float acc[2][4][4];
#pragma unroll
    for (int mt = 0; mt < 2; mt++)
#pragma unroll
        for (int nt = 0; nt < 4; nt++)
#pragma unroll
            for (int i = 0; i < 4; i++) acc[mt][nt][i] = 0.f;

    const float* Af = (const float*)Av;
    const __half* Ah = (const __half*)Av;

    float4 pa[4];
    uint2  pah[4];
    float  pb[2][4];
    const int nch = K / BK;

    /* prefetch chunk 0 */
    if (aHalf) {
#pragma unroll
        for (int p = 0; p < 4; p++)
            pah[p] = *(const uint2*)(Ah + (size_t)(row0 + arow + 32*p)*K + acol4);
    } else {
#pragma unroll
        for (int p = 0; p < 4; p++)
            pa[p] = *(const float4*)(Af + (size_t)(row0 + arow + 32*p)*K + acol4);
    }
#pragma unroll
    for (int p = 0; p < 2; p++)
#pragma unroll
        for (int j = 0; j < 4; j++)
            pb[p][j] = W[(size_t)(bk4 + 16*p + j)*N + col0 + bn];

    for (int c = 0; c < nch; c++) {
        if (aHalf) {
#pragma unroll
            for (int p = 0; p < 4; p++)
                *(uint2*)&As[arow + 32*p][acol4] = pah[p];
        } else {
#pragma unroll
            for (int p = 0; p < 4; p++) {
                uint2 h4;
                h4.x = h2pack(pa[p].x, pa[p].y);
                h4.y = h2pack(pa[p].z, pa[p].w);
                *(uint2*)&As[arow + 32*p][acol4] = h4;
            }
        }
#pragma unroll
        for (int p = 0; p < 2; p++) {
            uint2 h4;
            h4.x = h2pack(pb[p][0], pb[p][1]);
            h4.y = h2pack(pb[p][2], pb[p][3]);
            *(uint2*)&Bs[bn][bk4 + 16*p] = h4;
        }
        __syncthreads();

        if (c + 1 < nch) {
            int k0 = (c + 1) * BK;
            if (aHalf) {
#pragma unroll
                for (int p = 0; p < 4; p++)
                    pah[p] = *(const uint2*)(Ah + (size_t)(row0 + arow + 32*p)*K + k0 + acol4);
            } else {
#pragma unroll
                for (int p = 0; p < 4; p++)
                    pa[p] = *(const float4*)(Af + (size_t)(row0 + arow + 32*p)*K + k0 + acol4);
            }
#pragma unroll
            for (int p = 0; p < 2; p++)
#pragma unroll
                for (int j = 0; j < 4; j++)
                    pb[p][j] = W[(size_t)(k0 + bk4 + 16*p + j)*N + col0 + bn];
        }

        /* 2 k16-blocks: 8 ldsm + 16 mma */
#pragma unroll
        for (int kb = 0; kb < 2; kb++) {
            uint32_t af0[4], af1[4], bq0[4], bq1[4];
            ldsm4(af0, aB0 + kb*32);
            ldsm4(af1, aB1 + kb*32);
            ldsm4(bq0, bB0 + kb*32);
            ldsm4(bq1, bB1 + kb*32);
            mma_f16(acc[0][0], af0, &bq0[0]);
            mma_f16(acc[0][1], af0, &bq0[2]);
            mma_f16(acc[0][2], af0, &bq1[0]);
            mma_f16(acc[0][3], af0, &bq1[2]);
            mma_f16(acc[1][0], af1, &bq0[0]);
            mma_f16(acc[1][1], af1, &bq0[2]);
            mma_f16(acc[1][2], af1, &bq1[0]);
            mma_f16(acc[1][3], af1, &bq1[2]);
        }
        __syncthreads();
    }

    float* Cf = (float*)Cv;
    __half* Ch = (__half*)Cv;
#pragma unroll
    for (int mt = 0; mt < 2; mt++)
#pragma unroll
        for (int nt = 0; nt < 4; nt++) {
            int col = col0 + wn + nt*8 + cq*2;
            float b0 = bias[col], b1 = bias[col + 1];
#pragma unroll
            for (int hrow = 0; hrow < 2; hrow++) {
                int row = row0 + wm + mt*16 + r + hrow*8;
                float v0 = acc[mt][nt][hrow*2 + 0] + b0;
                float v1 = acc[mt][nt][hrow*2 + 1] + b1;
                if (act == 1) {
                    v0 = (v0 > 0.f) ? v0 : 0.2f*v0;
                    v1 = (v1 > 0.f) ? v1 : 0.2f*v1;
                } else if (act == 4) {
                    v0 *= QSCALE; v1 *= QSCALE;
                }
                if (act == 0) {
                    *(float2*)&Cf[(size_t)row*N + col] = make_float2(v0, v1);
                } else if (act == 3) {
                    int bb = row >> 11, token = row & (SEQ - 1);
                    int h0 = col >> 6, d0 = col & 63;
                    __half* dst = Ch + ((size_t)(bb*NHD + h0)*DK + d0)*SEQ + token;
                    dst[0]   = __float2half_rn(v0);
                    dst[SEQ] = __float2half_rn(v1);
                } else {
                    *(uint32_t*)&Ch[(size_t)row*N + col] = h2pack(v0, v1);
                }
            }
        }
}

/* =================== Flash attention, fp16 operands ====================== */
__global__ void __launch_bounds__(256, 2) flash_tc(
    const __half* __restrict__ Q, const __half* __restrict__ K,
    const __half* __restrict__ Vt, const int* __restrict__ mask,
    __half* __restrict__ Cv)
{
    extern __shared__ __align__(16) char smc[];
    __half* hsm = (__half*)smc;
    const uint32_t smBase = smem_u32(smc);
    const uint32_t smQ = smBase + HOFF_Q*2u;
    const uint32_t smK[2] = { smBase + HOFF_K*2u, smBase + (HOFF_K + KT*LDKH)*2u };
    const uint32_t smV[2] = { smBase + HOFF_V*2u, smBase + (HOFF_V + DK*LDVH)*2u };
    const uint32_t smM = smBase + HOFF_MB*2u;
    const int* MBI = (const int*)(smc + HOFF_MB*2);

    const int bh = blockIdx.y;
    const int b = bh >> 4, h = bh & 15;
    const int i0 = blockIdx.x * 128;
    const __half* Qp  = Q  + (size_t)b*SEQ*HID + h*DK;
    const __half* Kp  = K  + (size_t)b*SEQ*HID + h*DK;
    const __half* Vtp = Vt + (size_t)bh*DK*SEQ;
    const int* mrow = mask + b*SEQ;
    __half* Cp = Cv + (size_t)b*SEQ*HID + h*DK;

    const int tid = threadIdx.x;
    const int wid = tid >> 5, lane = tid & 31;
    const int wm = wid * 16;
    const int r = lane >> 2, cq = lane & 3;

    /* ---- prologue: Q tile (128 rows x 128B) + chunk 0 K/V + mask ---- */
#pragma unroll
    for (int p = 0; p < 4; p++) {
        int idx = p*256 + tid;
        int row = idx >> 3, u = idx & 7;
        cpa16(smQ + (uint32_t)(row*LDQH)*2u + u*16,
              Qp + (size_t)(i0 + row)*HID + u*8);
    }
    {
        int krow = tid >> 3, ku = tid & 7;
        cpa16(smK[0] + (uint32_t)(krow*LDKH)*2u + ku*16,
              Kp + (size_t)krow*HID + ku*8);
        int vrow = tid >> 2, vu = tid & 3;
        cpa16(smV[0] + (uint32_t)(vrow*LDVH)*2u + vu*16,
              Vtp + (size_t)vrow*SEQ + vu*8);
    }
    if (tid < 8) cpa16(smM + (uint32_t)(tid*16), mrow + tid*4);
    CPA_COMMIT();

    const uint32_t aQ = fb_m_h(smQ, wm, lane, LDQH);
    const uint32_t aP = fb_m_h(smBase + HOFF_P*2u, wm, lane, LDPH);
    uint32_t bK0[2], bK1[2], bVf[2][4];
#pragma unroll
    for (int buf = 0; buf < 2; buf++) {
        bK0[buf] = fb_n_h(smK[buf], 0,  lane, LDKH);
        bK1[buf] = fb_n_h(smK[buf], 16, lane, LDKH);
#pragma unroll
        for (int g = 0; g < 4; g++) bVf[buf][g] = fb_n_h(smV[buf], g*16, lane, LDVH);
    }

    float acc_o[8][4];
#pragma unroll
    for (int nt = 0; nt < 8; nt++)
#pragma unroll
        for (int i = 0; i < 4; i++) acc_o[nt][i] = 0.f;
    float m_st[2] = {-1e20f, -1e20f};
    float l_st[2] = {0.f, 0.f};

    for (int c = 0; c < NCH; c++) {
        const int cur = c & 1, nxt = cur ^ 1;

        CPA_WAIT0();
        __syncthreads();

        if (c + 1 < NCH) {
            const size_t k0 = (size_t)(c + 1) * KT;
            int krow = tid >> 3, ku = tid & 7;
            cpa16(smK[nxt] + (uint32_t)(krow*LDKH)*2u + ku*16,
                  Kp + (k0 + krow)*HID + ku*8);
            int vrow = tid >> 2, vu = tid & 3;
            cpa16(smV[nxt] + (uint32_t)(vrow*LDVH)*2u + vu*16,
                  Vtp + (size_t)vrow*SEQ + k0 + vu*8);
            if (tid < 8) cpa16(smM + (uint32_t)((nxt*KT + tid*4)*4), mrow + k0 + tid*4);
            CPA_COMMIT();
        }

        /* S = Q @ K^T : 4 k16-blocks, 12 ldsm + 16 mma */
        float acc_s[4][4];
#pragma unroll
        for (int nt = 0; nt < 4; nt++)
#pragma unroll
            for (int i = 0; i < 4; i++) acc_s[nt][i] = 0.f;
#pragma unroll
        for (int kb = 0; kb < 4; kb++) {
            uint32_t af[4], bq0[4], bq1[4];
            ldsm4(af,  aQ + kb*32);
            ldsm4(bq0, bK0[cur] + kb*32);
            ldsm4(bq1, bK1[cur] + kb*32);
            mma_f16(acc_s[0], af, &bq0[0]);
            mma_f16(acc_s[1], af, &bq0[2]);
            mma_f16(acc_s[2], af, &bq1[0]);
            mma_f16(acc_s[3], af, &bq1[2]);
        }

        /* base-2 online softmax (Q pre-scaled by 0.125*log2e) */
        const int* mi = MBI + cur*KT;
        float bias2[4][2];
#pragma unroll
        for (int nt = 0; nt < 4; nt++) {
            int j = nt*8 + cq*2;
            bias2[nt][0] = mi[j]     ? 0.f : -1e20f;
            bias2[nt][1] = mi[j + 1] ? 0.f : -1e20f;
        }
        float alpha[2];
#pragma unroll
        for (int rr = 0; rr < 2; rr++) {
            float mx = -3.4e38f;
#pragma unroll
            for (int nt = 0; nt < 4; nt++)
#pragma unroll
                for (int cc = 0; cc < 2; cc++) {
                    float s = acc_s[nt][rr*2+cc] + bias2[nt][cc];
                    acc_s[nt][rr*2+cc] = s;
                    mx = fmaxf(mx, s);
                }
            mx = fmaxf(mx, __shfl_xor_sync(0xffffffffu, mx, 1));
            mx = fmaxf(mx, __shfl_xor_sync(0xffffffffu, mx, 2));
            float m_new = fmaxf(m_st[rr], mx);
            float a = ex2(m_st[rr] - m_new);
            m_st[rr] = m_new;
            alpha[rr] = a;
            float lsum = 0.f;
#pragma unroll
            for (int nt = 0; nt < 4; nt++)
#pragma unroll
                for (int cc = 0; cc < 2; cc++) {
                    float p = ex2(acc_s[nt][rr*2+cc] - m_new);
                    acc_s[nt][rr*2+cc] = p;
                    lsum += p;
                }
            l_st[rr] = l_st[rr]*a + lsum;
        }
#pragma unroll
        for (int nt = 0; nt < 8; nt++)
#pragma unroll
            for (int i = 0; i < 4; i++) acc_o[nt][i] *= alpha[i>>1];

        /* write P as fp16 (warp-private rows) */
#pragma unroll
        for (int rr = 0; rr < 2; rr++) {
            int prow = wm + rr*8 + r;
#pragma unroll
            for (int nt = 0; nt < 4; nt++)
                *(uint32_t*)&hsm[HOFF_P + prow*LDPH + nt*8 + cq*2] =
                    h2pack(acc_s[nt][rr*2+0], acc_s[nt][rr*2+1]);
        }
        __syncwarp();

        /* O += P @ V : 2 k16-blocks, 10 ldsm + 16 mma */
#pragma unroll
        for (int kb = 0; kb < 2; kb++) {
            uint32_t af[4];
            ldsm4(af, aP + kb*32);
#pragma unroll
            for (int g = 0; g < 4; g++) {
                uint32_t bv[4];
                ldsm4(bv, bVf[cur][g] + kb*32);
                mma_f16(acc_o[2*g    ], af, &bv[0]);
                mma_f16(acc_o[2*g + 1], af, &bv[2]);
            }
        }
    }

    float inv2[2];
#pragma unroll
    for (int rr = 0; rr < 2; rr++) {
        float lt = l_st[rr];
        lt += __shfl_xor_sync(0xffffffffu, lt, 1);
        lt += __shfl_xor_sync(0xffffffffu, lt, 2);
        inv2[rr] = 1.f / lt;
    }
#pragma unroll
    for (int nt = 0; nt < 8; nt++) {
        int col = nt*8 + cq*2;
#pragma unroll
        for (int rr = 0; rr < 2; rr++) {
            int row = i0 + wm + rr*8 + r;
            *(uint32_t*)&Cp[(size_t)row*HID + col] =
                h2pack(acc_o[nt][rr*2+0]*inv2[rr], acc_o[nt][rr*2+1]*inv2[rr]);
        }
    }
}

/* ---------------- host orchestration ------------------------------------- */
extern "C" void kernel_launch(void* const* d_in, const int* in_sizes, int n_in,
                              void* d_out, int out_size)
{
    const float* query = (const float*)d_in[0];
    const float* key   = (const float*)d_in[1];
    const float* value = (const float*)d_in[2];
    const int*   mask  = (const int*)  d_in[3];
    const float* Wpq = (const float*)d_in[4],  *bpq = (const float*)d_in[5];
    const float* Wtq = (const float*)d_in[6],  *btq = (const float*)d_in[7];
    const float* Wpk = (const float*)d_in[8],  *bpk = (const float*)d_in[9];
    const float* Wtk = (const float*)d_in[10], *btk = (const float*)d_in[11];
    const float* Wpv = (const float*)d_in[12], *bpv = (const float*)d_in[13];
    const float* Wtv = (const float*)d_in[14], *btv = (const float*)d_in[15];
    const float* Wpo = (const float*)d_in[16], *bpo = (const float*)d_in[17];
    const float* Wto = (const float*)d_in[18], *bto = (const float*)d_in[19];
    float* out = (float*)d_out;

    __half *q_, *k_, *vt_, *h_, *cv_;
    cudaGetSymbolAddress((void**)&q_,  g_q);
    cudaGetSymbolAddress((void**)&k_,  g_k);
    cudaGetSymbolAddress((void**)&vt_, g_vt);
    cudaGetSymbolAddress((void**)&h_,  g_h);
    cudaGetSymbolAddress((void**)&cv_, g_cv);

    cudaFuncSetAttribute(flash_tc, cudaFuncAttributeMaxDynamicSharedMemorySize,
                         FLASH_SMEM);

    dim3 blk(256);
    dim3 gproj(ROWS/BM, FAC/BN);   /* (64, 4)  */
    dim3 gtran(ROWS/BM, HID/BN);   /* (64, 16) */

    linear_tc<<<gproj, blk>>>(query, Wpq, bpq, h_, ROWS, FAC, HID, 1, 0);
    linear_tc<<<gtran, blk>>>(h_,    Wtq, btq, q_, ROWS, HID, FAC, 4, 1);
    linear_tc<<<gproj, blk>>>(key,   Wpk, bpk, h_, ROWS, FAC, HID, 1, 0);
    linear_tc<<<gtran, blk>>>(h_,    Wtk, btk, k_, ROWS, HID, FAC, 2, 1);
    linear_tc<<<gproj, blk>>>(value, Wpv, bpv, h_, ROWS, FAC, HID, 1, 0);
    linear_tc<<<gtran, blk>>>(h_,    Wtv, btv, vt_, ROWS, HID, FAC, 3, 1);

    flash_tc<<<dim3(SEQ/128, BH), blk, FLASH_SMEM>>>(q_, k_, vt_, mask, cv_);

    linear_tc<<<gproj, blk>>>(cv_, Wpo, bpo, h_,  ROWS, FAC, HID, 1, 1);
    linear_tc<<<gtran, blk>>>(h_,  Wto, bto, out, ROWS, HID, FAC, 0, 1);
}

// round 15
// speedup vs baseline: 1.7861x; 1.1093x over previous
#include <cuda_runtime.h>
#include <cuda_fp16.h>
#include <math.h>
#include <stdint.h>

#define NB   4
#define SEQ  2048
#define HID  1024
#define FAC  256
#define NHD  16
#define DK   64
#define ROWS (NB*SEQ)   /* 8192 */
#define BH   (NB*NHD)   /* 64   */

/* linear tiling: 128x64 block, 8 warps of 32x32, fp16 operands */
#define BM 128
#define BN 64
#define BK 32
#define LDA_H 40
#define LDB_H 40

/* flash geometry: fp16 operands, KT=64 */
#define KT   64
#define NCH  (SEQ/KT)    /* 32 */
#define LDH  72          /* uniform 144B row stride */
#define HOFF_Q  0
#define HOFF_K  (128*LDH)               /* 9216  */
#define HOFF_V  (HOFF_K + 2*KT*LDH)     /* 18432 */
#define HOFF_P  (HOFF_V + 2*DK*LDH)     /* 27648 */
#define HOFF_MB (HOFF_P + 128*LDH)      /* 36864 halves = 73728 B */
#define FLASH_SMEM (HOFF_MB*2 + 2*KT*4) /* 74240 B */

/* 0.125 * log2(e): Q prescale so scores land in the log2 domain */
#define QSCALE 0.1803368801111204f

/* ---------------- scratch ------------------------------------------------ */
__device__ __half g_q  [ROWS*HID];
__device__ __half g_k  [ROWS*HID];
__device__ __half g_vt [BH*DK*SEQ];   /* V transposed: [bh][d][token] */
__device__ __half g_h  [ROWS*FAC];
__device__ __half g_cv [ROWS*HID];

/* ---------------- helpers ------------------------------------------------ */
__device__ __forceinline__ uint32_t h2pack(float a, float b) {
    __half2 h = __floats2half2_rn(a, b);
    return *(uint32_t*)&h;
}
__device__ __forceinline__ float ex2(float x) {
    float y;
    asm("ex2.approx.f32 %0, %1;" : "=f"(y) : "f"(x));
    return y;
}
__device__ __forceinline__ void mma_f16(float c[4], const uint32_t a[4], const uint32_t b[2]) {
    asm volatile(
        "mma.sync.aligned.m16n8k16.row.col.f32.f16.f16.f32 "
        "{%0,%1,%2,%3}, {%4,%5,%6,%7}, {%8,%9}, {%0,%1,%2,%3};"
        : "+f"(c[0]), "+f"(c[1]), "+f"(c[2]), "+f"(c[3])
        : "r"(a[0]), "r"(a[1]), "r"(a[2]), "r"(a[3]), "r"(b[0]), "r"(b[1]));
}
__device__ __forceinline__ void ldsm4(uint32_t f[4], uint32_t addr) {
    asm volatile("ldmatrix.sync.aligned.m8n8.x4.shared.b16 {%0,%1,%2,%3}, [%4];"
        : "=r"(f[0]), "=r"(f[1]), "=r"(f[2]), "=r"(f[3]) : "r"(addr));
}
__device__ __forceinline__ uint32_t smem_u32(const void* p) {
    return (uint32_t)__cvta_generic_to_shared(p);
}
__device__ __forceinline__ void cpa16(uint32_t dst, const void* src) {
    asm volatile("cp.async.cg.shared.global [%0], [%1], 16;" :: "r"(dst), "l"(src));
}
#define CPA_COMMIT() asm volatile("cp.async.commit_group;" ::: "memory")
#define CPA_WAIT0()  asm volatile("cp.async.wait_group 0;" ::: "memory")

__device__ __forceinline__ uint32_t fb_m_h(uint32_t base, int row0, int lane, int ldh) {
    int lr = lane & 7, sel = lane >> 3;
    int row = row0 + lr + ((sel & 1) << 3);
    int colb = (sel & 2) * 8;
    return base + (uint32_t)(row*ldh)*2u + colb;
}
__device__ __forceinline__ uint32_t fb_n_h(uint32_t base, int n0, int lane, int ldh) {
    int lr = lane & 7, sel = lane >> 3;
    int row = n0 + lr + ((sel & 2) << 2);
    int colb = (sel & 1) * 16;
    return base + (uint32_t)(row*ldh)*2u + colb;
}

/* =================== fp16 linear (templated A dtype) =====================
   act: 0 = bias, fp32 out; 1 = bias+leaky(0.2), half out;
        2 = bias, half out; 3 = bias, half TRANSPOSED into Vt[bh][d][token];
        4 = bias*QSCALE, half out (Q, log2 domain)                          */
template <int AH>
__global__ void __launch_bounds__(256, 3) linear_tc(
    const void* __restrict__ Av, const float* __restrict__ W,
    const float* __restrict__ bias, void* __restrict__ Cv,
    int M, int N, int K, int act)
{
    __shared__ __align__(16) __half As[BM][LDA_H];
    __shared__ __align__(16) __half Bs[BN][LDB_H];

    const int tid = threadIdx.x;
    const int row0 = blockIdx.x * BM;
    const int col0 = blockIdx.y * BN;

    const int arow = tid >> 3, acol4 = (tid & 7) << 2;
    const int bn = tid & 63, bk4 = (tid >> 6) << 2;

    const int wid = tid >> 5, lane = tid & 31;
    const int wm = (wid >> 1) * 32, wn = (wid & 1) * 32;
    const int r = lane >> 2, cq = lane & 3;

    const uint32_t smA = smem_u32(&As[0][0]);
    const uint32_t smB = smem_u32(&Bs[0][0]);
    const uint32_t aB0 = fb_m_h(smA, wm,      lane, LDA_H);
    const uint32_t aB1 = fb_m_h(smA, wm + 16, lane, LDA_H);
    const uint32_t bB0 = fb_n_h(smB, wn,      lane, LDB_H);
    const uint32_t bB1 = fb_n_h(smB, wn + 16, lane, LDB_H);

    float acc[2][4][4];
#pragma unroll
    for (int mt = 0; mt < 2; mt++)
#pragma unroll
        for (int nt = 0; nt < 4; nt++)
#pragma unroll
            for (int i = 0; i < 4; i++) acc[mt][nt][i] = 0.f;

    const float* Af = (const float*)Av;
    const __half* Ah = (const __half*)Av;

    float4 pa[4];
    uint2  pah[4];
    float  pb[2][4];
    const int nch = K / BK;

    if (AH) {
#pragma unroll
        for (int p = 0; p < 4; p++)
            pah[p] = *(const uint2*)(Ah + (size_t)(row0 + arow + 32*p)*K + acol4);
    } else {
#pragma unroll
        for (int p = 0; p < 4; p++)
            pa[p] = *(const float4*)(Af + (size_t)(row0 + arow + 32*p)*K + acol4);
    }
#pragma unroll
    for (int p = 0; p < 2; p++)
#pragma unroll
        for (int j = 0; j < 4; j++)
            pb[p][j] = W[(size_t)(bk4 + 16*p + j)*N + col0 + bn];

    for (int c = 0; c < nch; c++) {
        if (AH) {
#pragma unroll
            for (int p = 0; p < 4; p++)
                *(uint2*)&As[arow + 32*p][acol4] = pah[p];
        } else {
#pragma unroll
            for (int p = 0; p < 4; p++) {
                uint2 h4;
                h4.x = h2pack(pa[p].x, pa[p].y);
                h4.y = h2pack(pa[p].z, pa[p].w);
                *(uint2*)&As[arow + 32*p][acol4] = h4;
            }
        }
#pragma unroll
        for (int p = 0; p < 2; p++) {
            uint2 h4;
            h4.x = h2pack(pb[p][0], pb[p][1]);
            h4.y = h2pack(pb[p][2], pb[p][3]);
            *(uint2*)&Bs[bn][bk4 + 16*p] = h4;
        }
        __syncthreads();

        if (c + 1 < nch) {
            int k0 = (c + 1) * BK;
            if (AH) {
#pragma unroll
                for (int p = 0; p < 4; p++)
                    pah[p] = *(const uint2*)(Ah + (size_t)(row0 + arow + 32*p)*K + k0 + acol4);
            } else {
#pragma unroll
                for (int p = 0; p < 4; p++)
                    pa[p] = *(const float4*)(Af + (size_t)(row0 + arow + 32*p)*K + k0 + acol4);
            }
#pragma unroll
            for (int p = 0; p < 2; p++)
#pragma unroll
                for (int j = 0; j < 4; j++)
                    pb[p][j] = W[(size_t)(k0 + bk4 + 16*p + j)*N + col0 + bn];
        }

#pragma unroll
        for (int kb = 0; kb < 2; kb++) {
            uint32_t af0[4], af1[4], bq0[4], bq1[4];
            ldsm4(af0, aB0 + kb*32);
            ldsm4(af1, aB1 + kb*32);
            ldsm4(bq0, bB0 + kb*32);
            ldsm4(bq1, bB1 + kb*32);
            mma_f16(acc[0][0], af0, &bq0[0]);
            mma_f16(acc[0][1], af0, &bq0[2]);
            mma_f16(acc[0][2], af0, &bq1[0]);
            mma_f16(acc[0][3], af0, &bq1[2]);
            mma_f16(acc[1][0], af1, &bq0[0]);
            mma_f16(acc[1][1], af1, &bq0[2]);
            mma_f16(acc[1][2], af1, &bq1[0]);
            mma_f16(acc[1][3], af1, &bq1[2]);
        }
        __syncthreads();
    }

    float* Cf = (float*)Cv;
    __half* Ch = (__half*)Cv;
#pragma unroll
    for (int mt = 0; mt < 2; mt++)
#pragma unroll
        for (int nt = 0; nt < 4; nt++) {
            int col = col0 + wn + nt*8 + cq*2;
            float b0 = bias[col], b1 = bias[col + 1];
#pragma unroll
            for (int hrow = 0; hrow < 2; hrow++) {
                int row = row0 + wm + mt*16 + r + hrow*8;
                float v0 = acc[mt][nt][hrow*2 + 0] + b0;
                float v1 = acc[mt][nt][hrow*2 + 1] + b1;
                if (act == 1) {
                    v0 = (v0 > 0.f) ? v0 : 0.2f*v0;
                    v1 = (v1 > 0.f) ? v1 : 0.2f*v1;
                } else if (act == 4) {
                    v0 *= QSCALE; v1 *= QSCALE;
                }
                if (act == 0) {
                    *(float2*)&Cf[(size_t)row*N + col] = make_float2(v0, v1);
                } else if (act == 3) {
                    int bb = row >> 11, token = row & (SEQ - 1);
                    int h0 = col >> 6, d0 = col & 63;
                    __half* dst = Ch + ((size_t)(bb*NHD + h0)*DK + d0)*SEQ + token;
                    dst[0]   = __float2half_rn(v0);
                    dst[SEQ] = __float2half_rn(v1);
                } else {
                    *(uint32_t*)&Ch[(size_t)row*N + col] = h2pack(v0, v1);
                }
            }
        }
}

/* =================== Flash attention, fp16, KT=64 ======================== */
__global__ void __launch_bounds__(256, 2) flash_tc(
    const __half* __restrict__ Q, const __half* __restrict__ K,
    const __half* __restrict__ Vt, const int* __restrict__ mask,
    __half* __restrict__ Cv)
{
    extern __shared__ __align__(16) char smc[];
    __half* hsm = (__half*)smc;
    const uint32_t smBase = smem_u32(smc);
    const uint32_t smQ = smBase + HOFF_Q*2u;
    const uint32_t smK[2] = { smBase + HOFF_K*2u, smBase + (HOFF_K + KT*LDH)*2u };
    const uint32_t smV[2] = { smBase + HOFF_V*2u, smBase + (HOFF_V + DK*LDH)*2u };
    const uint32_t smM = smBase + HOFF_MB*2u;
    const int* MBI = (const int*)(smc + HOFF_MB*2);

    const int bh = blockIdx.y;
    const int b = bh >> 4, h = bh & 15;
    const int i0 = blockIdx.x * 128;
    const __half* Qp  = Q  + (size_t)b*SEQ*HID + h*DK;
    const __half* Kp  = K  + (size_t)b*SEQ*HID + h*DK;
    const __half* Vtp = Vt + (size_t)bh*DK*SEQ;
    const int* mrow = mask + b*SEQ;
    __half* Cp = Cv + (size_t)b*SEQ*HID + h*DK;

    const int tid = threadIdx.x;
    const int wid = tid >> 5, lane = tid & 31;
    const int wm = wid * 16;
    const int r = lane >> 2, cq = lane & 3;

    /* prologue: Q tile + chunk 0 K/V + mask */
#pragma unroll
    for (int p = 0; p < 4; p++) {
        int idx = p*256 + tid;
        int row = idx >> 3, u = idx & 7;
        cpa16(smQ + (uint32_t)(row*LDH)*2u + u*16,
              Qp + (size_t)(i0 + row)*HID + u*8);
    }
#pragma unroll
    for (int p = 0; p < 2; p++) {
        int idx = p*256 + tid;
        int krow = idx >> 3, ku = idx & 7;
        cpa16(smK[0] + (uint32_t)(krow*LDH)*2u + ku*16,
              Kp + (size_t)krow*HID + ku*8);
        cpa16(smV[0] + (uint32_t)(krow*LDH)*2u + ku*16,
              Vtp + (size_t)krow*SEQ + ku*8);
    }
    if (tid < 16) cpa16(smM + (uint32_t)(tid*16), mrow + tid*4);
    CPA_COMMIT();

    const uint32_t aQ = fb_m_h(smQ, wm, lane, LDH);
    const uint32_t aP = fb_m_h(smBase + HOFF_P*2u, wm, lane, LDH);
    uint32_t bKf[2][4], bVf[2][4];
#pragma unroll
    for (int buf = 0; buf < 2; buf++)
#pragma unroll
        for (int g = 0; g < 4; g++) {
            bKf[buf][g] = fb_n_h(smK[buf], g*16, lane, LDH);
            bVf[buf][g] = fb_n_h(smV[buf], g*16, lane, LDH);
        }

    float acc_o[8][4];
#pragma unroll
    for (int nt = 0; nt < 8; nt++)
#pragma unroll
        for (int i = 0; i < 4; i++) acc_o[nt][i] = 0.f;
    float m_st[2] = {-1e20f, -1e20f};
    float l_st[2] = {0.f, 0.f};

    for (int c = 0; c < NCH; c++) {
        const int cur = c & 1, nxt = cur ^ 1;

        CPA_WAIT0();
        __syncthreads();

        if (c + 1 < NCH) {
            const size_t k0 = (size_t)(c + 1) * KT;
#pragma unroll
            for (int p = 0; p < 2; p++) {
                int idx = p*256 + tid;
                int krow = idx >> 3, ku = idx & 7;
                cpa16(smK[nxt] + (uint32_t)(krow*LDH)*2u + ku*16,
                      Kp + (k0 + krow)*HID + ku*8);
                cpa16(smV[nxt] + (uint32_t)(krow*LDH)*2u + ku*16,
                      Vtp + (size_t)krow*SEQ + k0 + ku*8);
            }
            if (tid < 16) cpa16(smM + (uint32_t)((nxt*KT + tid*4)*4), mrow + k0 + tid*4);
            CPA_COMMIT();
        }

        /* S = Q @ K^T : 16 rows x 64 keys, 4 k16-blocks: 20 ldsm + 32 mma */
        float acc_s[8][4];
#pragma unroll
        for (int nt = 0; nt < 8; nt++)
#pragma unroll
            for (int i = 0; i < 4; i++) acc_s[nt][i] = 0.f;
#pragma unroll
        for (int kb = 0; kb < 4; kb++) {
            uint32_t af[4];
            ldsm4(af, aQ + kb*32);
#pragma unroll
            for (int g = 0; g < 4; g++) {
                uint32_t bq[4];
                ldsm4(bq, bKf[cur][g] + kb*32);
                mma_f16(acc_s[2*g    ], af, &bq[0]);
                mma_f16(acc_s[2*g + 1], af, &bq[2]);
            }
        }

        /* base-2 online softmax over 64 keys (warp-local rows) */
        const int* mi = MBI + cur*KT;
        float alpha[2];
#pragma unroll
        for (int rr = 0; rr < 2; rr++) {
            float mx = -3.4e38f;
#pragma unroll
            for (int nt = 0; nt < 8; nt++) {
                int j = nt*8 + cq*2;
                float b0 = mi[j]     ? 0.f : -1e20f;
                float b1 = mi[j + 1] ? 0.f : -1e20f;
                float s0 = acc_s[nt][rr*2+0] + b0;
                float s1 = acc_s[nt][rr*2+1] + b1;
                acc_s[nt][rr*2+0] = s0;
                acc_s[nt][rr*2+1] = s1;
                mx = fmaxf(mx, fmaxf(s0, s1));
            }
            mx = fmaxf(mx, __shfl_xor_sync(0xffffffffu, mx, 1));
            mx = fmaxf(mx, __shfl_xor_sync(0xffffffffu, mx, 2));
            float m_new = fmaxf(m_st[rr], mx);
            float a = ex2(m_st[rr] - m_new);
            m_st[rr] = m_new;
            alpha[rr] = a;
            float lsum = 0.f;
#pragma unroll
            for (int nt = 0; nt < 8; nt++)
#pragma unroll
                for (int cc = 0; cc < 2; cc++) {
                    float p = ex2(acc_s[nt][rr*2+cc] - m_new);
                    acc_s[nt][rr*2+cc] = p;
                    lsum += p;
                }
            l_st[rr] = l_st[rr]*a + lsum;
        }
#pragma unroll
        for (int nt = 0; nt < 8; nt++)
#pragma unroll
            for (int i = 0; i < 4; i++) acc_o[nt][i] *= alpha[i>>1];

        /* write P as fp16 (warp-private rows) */
#pragma unroll
        for (int rr = 0; rr < 2; rr++) {
            int prow = wm + rr*8 + r;
#pragma unroll
            for (int nt = 0; nt < 8; nt++)
                *(uint32_t*)&hsm[HOFF_P + prow*LDH + nt*8 + cq*2] =
                    h2pack(acc_s[nt][rr*2+0], acc_s[nt][rr*2+1]);
        }
        __syncwarp();

        /* O += P @ V : 4 k16-blocks: 20 ldsm + 32 mma */
#pragma unroll
        for (int kb = 0; kb < 4; kb++) {
            uint32_t af[4];
            ldsm4(af, aP + kb*32);
#pragma unroll
            for (int g = 0; g < 4; g++) {
                uint32_t bv[4];
                ldsm4(bv, bVf[cur][g] + kb*32);
                mma_f16(acc_o[2*g    ], af, &bv[0]);
                mma_f16(acc_o[2*g + 1], af, &bv[2]);
            }
        }
    }

    float inv2[2];
#pragma unroll
    for (int rr = 0; rr < 2; rr++) {
        float lt = l_st[rr];
        lt += __shfl_xor_sync(0xffffffffu, lt, 1);
        lt += __shfl_xor_sync(0xffffffffu, lt, 2);
        inv2[rr] = 1.f / lt;
    }
#pragma unroll
    for (int nt = 0; nt < 8; nt++) {
        int col = nt*8 + cq*2;
#pragma unroll
        for (int rr = 0; rr < 2; rr++) {
            int row = i0 + wm + rr*8 + r;
            *(uint32_t*)&Cp[(size_t)row*HID + col] =
                h2pack(acc_o[nt][rr*2+0]*inv2[rr], acc_o[nt][rr*2+1]*inv2[rr]);
        }
    }
}

/* ---------------- host orchestration ------------------------------------- */
extern "C" void kernel_launch(void* const* d_in, const int* in_sizes, int n_in,
                              void* d_out, int out_size)
{
    const float* query = (const float*)d_in[0];
    const float* key   = (const float*)d_in[1];
    const float* value = (const float*)d_in[2];
    const int*   mask  = (const int*)  d_in[3];
    const float* Wpq = (const float*)d_in[4],  *bpq = (const float*)d_in[5];
    const float* Wtq = (const float*)d_in[6],  *btq = (const float*)d_in[7];
    const float* Wpk = (const float*)d_in[8],  *bpk = (const float*)d_in[9];
    const float* Wtk = (const float*)d_in[10], *btk = (const float*)d_in[11];
    const float* Wpv = (const float*)d_in[12], *bpv = (const float*)d_in[13];
    const float* Wtv = (const float*)d_in[14], *btv = (const float*)d_in[15];
    const float* Wpo = (const float*)d_in[16], *bpo = (const float*)d_in[17];
    const float* Wto = (const float*)d_in[18], *bto = (const float*)d_in[19];
    float* out = (float*)d_out;

    __half *q_, *k_, *vt_, *h_, *cv_;
    cudaGetSymbolAddress((void**)&q_,  g_q);
    cudaGetSymbolAddress((void**)&k_,  g_k);
    cudaGetSymbolAddress((void**)&vt_, g_vt);
    cudaGetSymbolAddress((void**)&h_,  g_h);
    cudaGetSymbolAddress((void**)&cv_, g_cv);

    cudaFuncSetAttribute(flash_tc, cudaFuncAttributeMaxDynamicSharedMemorySize,
                         FLASH_SMEM);

    dim3 blk(256);
    dim3 gproj(ROWS/BM, FAC/BN);   /* (64, 4)  */
    dim3 gtran(ROWS/BM, HID/BN);   /* (64, 16) */

    linear_tc<0><<<gproj, blk>>>(query, Wpq, bpq, h_, ROWS, FAC, HID, 1);
    linear_tc<1><<<gtran, blk>>>(h_,    Wtq, btq, q_, ROWS, HID, FAC, 4);
    linear_tc<0><<<gproj, blk>>>(key,   Wpk, bpk, h_, ROWS, FAC, HID, 1);
    linear_tc<1><<<gtran, blk>>>(h_,    Wtk, btk, k_, ROWS, HID, FAC, 2);
    linear_tc<0><<<gproj, blk>>>(value, Wpv, bpv, h_, ROWS, FAC, HID, 1);
    linear_tc<1><<<gtran, blk>>>(h_,    Wtv, btv, vt_, ROWS, HID, FAC, 3);

    flash_tc<<<dim3(SEQ/128, BH), blk, FLASH_SMEM>>>(q_, k_, vt_, mask, cv_);

    linear_tc<1><<<gproj, blk>>>(cv_, Wpo, bpo, h_,  ROWS, FAC, HID, 1);
    linear_tc<1><<<gtran, blk>>>(h_,  Wto, bto, out, ROWS, HID, FAC, 0);
}